// round 14
// baseline (speedup 1.0000x reference)
#include <cuda_runtime.h>
#include <math.h>
#include <stdint.h>

#define N_NODES 100000
#define N_EDGES 1600000
#define D_IN    384
#define D_HID   768
#define D_OUT   256

// ---------------- scratch (device globals: no allocation allowed) ----------
__device__ __align__(16) float g_h1 [(size_t)N_NODES * D_HID];  // 307 MB (pre-LN, then LN'd in place)
__device__ __align__(16) float g_h  [(size_t)N_NODES * D_OUT];  // 102 MB
__device__ __align__(16) float g_sum[(size_t)N_NODES * D_OUT];  // 102 MB
__device__ __align__(16) float g_p  [(size_t)N_NODES * D_OUT];  // 102 MB (sage pre-LN)
__device__ __align__(16) float g_cnt[N_NODES];
__device__ __align__(16) float g_inv[N_NODES];
__device__ int g_is64;

// ---------------- helpers ----------------------------------------------------
__device__ __forceinline__ float to_tf32(float x) {
    float r;
    asm("cvt.rna.tf32.f32 %0, %1;" : "=f"(r) : "f"(x));
    return r;
}

__device__ __forceinline__ void mma_tf32(float* c, const uint32_t* a, const uint32_t* b) {
    asm volatile(
        "mma.sync.aligned.m16n8k8.row.col.f32.tf32.tf32.f32 "
        "{%0,%1,%2,%3}, {%4,%5,%6,%7}, {%8,%9}, {%0,%1,%2,%3};\n"
        : "+f"(c[0]), "+f"(c[1]), "+f"(c[2]), "+f"(c[3])
        : "r"(a[0]), "r"(a[1]), "r"(a[2]), "r"(a[3]), "r"(b[0]), "r"(b[1]));
}

// ---------------- K0: zero accumulators + detect edge_index dtype ----------
__global__ void k_zero(const void* __restrict__ ei_raw)
{
    size_t i      = (size_t)blockIdx.x * blockDim.x + threadIdx.x;
    size_t stride = (size_t)gridDim.x * blockDim.x;
    size_t n4     = (size_t)N_NODES * D_OUT / 4;
    float4 z = make_float4(0.f, 0.f, 0.f, 0.f);
    for (size_t j = i; j < n4; j += stride)
        reinterpret_cast<float4*>(g_sum)[j] = z;
    for (size_t j = i; j < N_NODES; j += stride)
        g_cnt[j] = 0.f;

    if (blockIdx.x == 0 && threadIdx.x == 0) {
        const unsigned int* w = (const unsigned int*)ei_raw;
        int is64 = 1;
        for (int k = 0; k < 64; k++)
            if (w[2 * k + 1] != 0u) is64 = 0;
        g_is64 = is64;
    }
}

// ---------------- tf32 GEMM: C[M,NN] = A[M,KTOT] @ B[KTOT,NN] + bias ---------
// Block tile 128x64, 4 warps (2x2), each warp 64x32 (4x4 m16n8k8 tiles), BK=16.
// SPLIT: K in [0,256) reads A0*inv[row] with B0; K in [256,512) reads A1 with B1.
template<int KTOT, int NN, int AST, bool SPLIT>
__global__ __launch_bounds__(128)
void k_gemm(const float* __restrict__ A0, const float* __restrict__ A1,
            const float* __restrict__ B0, const float* __restrict__ B1,
            const float* __restrict__ inv, const float* __restrict__ bias,
            float* __restrict__ Cout)
{
    constexpr int BM = 128, BN = 64, BK = 16;
    constexpr int ASW = BM + 4;   // 132: conflict-free frag loads
    constexpr int BSW = BN + 4;   // 68

    __shared__ float As[BK][ASW];
    __shared__ float Bs[BK][BSW];

    const int bn0  = blockIdx.x * BN;
    const int bm0  = blockIdx.y * BM;
    const int tid  = threadIdx.x;
    const int lane = tid & 31, wid = tid >> 5;
    const int gid  = lane >> 2, tig = lane & 3;
    const int wm0  = (wid & 1) * 64;
    const int wn0  = (wid >> 1) * 32;

    // A loader: thread covers rows rb+32j (j=0..3), k-quad qi (4 consecutive k)
    const int qi = tid & 3;
    const int rb = tid >> 2;

    float4 ra[4];
    float4 rbv[2];
    float  acc[4][4][4];
#pragma unroll
    for (int mt = 0; mt < 4; mt++)
#pragma unroll
        for (int nt = 0; nt < 4; nt++)
#pragma unroll
            for (int j = 0; j < 4; j++) acc[mt][nt][j] = 0.f;

    auto loadA = [&](int k0) {
#pragma unroll
        for (int j = 0; j < 4; j++) {
            int row = bm0 + rb + 32 * j;
            float4 v = make_float4(0.f, 0.f, 0.f, 0.f);
            if (row < N_NODES) {
                if (!SPLIT || k0 < 256) {
                    v = *reinterpret_cast<const float4*>(A0 + (size_t)row * AST + k0 + qi * 4);
                    if (SPLIT) {
                        float s = inv[row];
                        v.x *= s; v.y *= s; v.z *= s; v.w *= s;
                    }
                } else {
                    v = *reinterpret_cast<const float4*>(A1 + (size_t)row * AST + (k0 - 256) + qi * 4);
                }
            }
            ra[j] = v;
        }
    };

    auto loadB = [&](int k0) {
#pragma unroll
        for (int j = 0; j < 2; j++) {
            int idx = tid + 128 * j;
            int kb = idx >> 4, nq = idx & 15;
            const float* Bp;
            if (!SPLIT || k0 < 256) Bp = B0 + (size_t)(k0 + kb) * NN;
            else                    Bp = B1 + (size_t)(k0 - 256 + kb) * NN;
            rbv[j] = *reinterpret_cast<const float4*>(Bp + bn0 + nq * 4);
        }
    };

    auto storeS = [&]() {
#pragma unroll
        for (int j = 0; j < 4; j++) {
            int r = rb + 32 * j;
            As[qi * 4 + 0][r] = to_tf32(ra[j].x);
            As[qi * 4 + 1][r] = to_tf32(ra[j].y);
            As[qi * 4 + 2][r] = to_tf32(ra[j].z);
            As[qi * 4 + 3][r] = to_tf32(ra[j].w);
        }
#pragma unroll
        for (int j = 0; j < 2; j++) {
            int idx = tid + 128 * j;
            int kb = idx >> 4, nq = idx & 15;
            float4 v = rbv[j];
            v.x = to_tf32(v.x); v.y = to_tf32(v.y);
            v.z = to_tf32(v.z); v.w = to_tf32(v.w);
            *reinterpret_cast<float4*>(&Bs[kb][nq * 4]) = v;
        }
    };

    auto compute = [&]() {
#pragma unroll
        for (int s = 0; s < 2; s++) {
            const int kk = s * 8;
            uint32_t af[4][4], bf[4][2];
#pragma unroll
            for (int mt = 0; mt < 4; mt++) {
                int m = wm0 + mt * 16 + gid;
                af[mt][0] = __float_as_uint(As[kk + tig    ][m]);
                af[mt][1] = __float_as_uint(As[kk + tig    ][m + 8]);
                af[mt][2] = __float_as_uint(As[kk + tig + 4][m]);
                af[mt][3] = __float_as_uint(As[kk + tig + 4][m + 8]);
            }
#pragma unroll
            for (int nt = 0; nt < 4; nt++) {
                int n = wn0 + nt * 8 + gid;
                bf[nt][0] = __float_as_uint(Bs[kk + tig    ][n]);
                bf[nt][1] = __float_as_uint(Bs[kk + tig + 4][n]);
            }
#pragma unroll
            for (int mt = 0; mt < 4; mt++)
#pragma unroll
                for (int nt = 0; nt < 4; nt++)
                    mma_tf32(acc[mt][nt], af[mt], bf[nt]);
        }
    };

    loadA(0);
    loadB(0);
    for (int k0 = 0; k0 < KTOT; k0 += BK) {
        __syncthreads();
        storeS();
        __syncthreads();
        if (k0 + BK < KTOT) { loadA(k0 + BK); loadB(k0 + BK); }
        compute();
    }

    // epilogue: + bias, store fp32
#pragma unroll
    for (int mt = 0; mt < 4; mt++) {
        int r0 = bm0 + wm0 + mt * 16 + gid;
#pragma unroll
        for (int nt = 0; nt < 4; nt++) {
            int c = bn0 + wn0 + nt * 8 + 2 * tig;
            float2 bv = *reinterpret_cast<const float2*>(bias + c);
            if (r0 < N_NODES) {
                float2 o = make_float2(acc[mt][nt][0] + bv.x, acc[mt][nt][1] + bv.y);
                *reinterpret_cast<float2*>(Cout + (size_t)r0 * NN + c) = o;
            }
            if (r0 + 8 < N_NODES) {
                float2 o = make_float2(acc[mt][nt][2] + bv.x, acc[mt][nt][3] + bv.y);
                *reinterpret_cast<float2*>(Cout + (size_t)(r0 + 8) * NN + c) = o;
            }
        }
    }
}

// ---------------- LN1: g_h1 = GELU(LN(g_h1) * g1 + be1), in place -----------
// One warp per row (768 cols = 6 float4 per lane).
__global__ __launch_bounds__(256)
void k_ln1(const float* __restrict__ g1, const float* __restrict__ be1)
{
    int row  = blockIdx.x * 8 + (threadIdx.x >> 5);
    int lane = threadIdx.x & 31;
    if (row >= N_NODES) return;
    float* p = g_h1 + (size_t)row * D_HID;

    float4 v[6];
    float s = 0.f, q = 0.f;
#pragma unroll
    for (int j = 0; j < 6; j++) {
        v[j] = *reinterpret_cast<const float4*>(p + (lane + 32 * j) * 4);
        s += v[j].x + v[j].y + v[j].z + v[j].w;
        q += v[j].x * v[j].x + v[j].y * v[j].y + v[j].z * v[j].z + v[j].w * v[j].w;
    }
#pragma unroll
    for (int o = 16; o > 0; o >>= 1) {
        s += __shfl_xor_sync(0xffffffffu, s, o);
        q += __shfl_xor_sync(0xffffffffu, q, o);
    }
    float mu = s * (1.f / D_HID);
    float rs = rsqrtf(q * (1.f / D_HID) - mu * mu + 1e-5f);

#pragma unroll
    for (int j = 0; j < 6; j++) {
        int c = (lane + 32 * j) * 4;
        float4 gg = *reinterpret_cast<const float4*>(g1  + c);
        float4 bt = *reinterpret_cast<const float4*>(be1 + c);
        float4 o;
        float t;
        t = (v[j].x - mu) * rs * gg.x + bt.x; o.x = 0.5f * t * (1.f + erff(t * 0.70710678118654752f));
        t = (v[j].y - mu) * rs * gg.y + bt.y; o.y = 0.5f * t * (1.f + erff(t * 0.70710678118654752f));
        t = (v[j].z - mu) * rs * gg.z + bt.z; o.z = 0.5f * t * (1.f + erff(t * 0.70710678118654752f));
        t = (v[j].w - mu) * rs * gg.w + bt.w; o.w = 0.5f * t * (1.f + erff(t * 0.70710678118654752f));
        *reinterpret_cast<float4*>(p + c) = o;
    }
}

// ---------------- K3: edge scatter (segment-sum + counts) -------------------
__global__ void k_scatter(const void* __restrict__ ei_raw)
{
    int gw   = (int)(((size_t)blockIdx.x * blockDim.x + threadIdx.x) >> 5);
    int lane = threadIdx.x & 31;
    if (gw >= N_EDGES) return;

    int s, d;
    if (g_is64) {
        const long long* e = (const long long*)ei_raw;
        s = (int)e[gw];
        d = (int)e[(size_t)N_EDGES + gw];
    } else {
        const int* e = (const int*)ei_raw;
        s = e[gw];
        d = e[N_EDGES + gw];
    }

    const float4* hp = reinterpret_cast<const float4*>(g_h + (size_t)s * D_OUT);
    float*        sp = g_sum + (size_t)d * D_OUT;

    float4 v0 = hp[lane];
    float4 v1 = hp[lane + 32];
    int b0 = lane * 4;
    atomicAdd(sp + b0 + 0, v0.x);
    atomicAdd(sp + b0 + 1, v0.y);
    atomicAdd(sp + b0 + 2, v0.z);
    atomicAdd(sp + b0 + 3, v0.w);
    atomicAdd(sp + 128 + b0 + 0, v1.x);
    atomicAdd(sp + 128 + b0 + 1, v1.y);
    atomicAdd(sp + 128 + b0 + 2, v1.z);
    atomicAdd(sp + 128 + b0 + 3, v1.w);
    if (lane == 0) atomicAdd(&g_cnt[d], 1.0f);
}

// ---------------- inv counts -------------------------------------------------
__global__ void k_inv()
{
    int i = blockIdx.x * 256 + threadIdx.x;
    if (i < N_NODES) g_inv[i] = 1.f / fmaxf(g_cnt[i], 1.f);
}

// ---------------- LN2: out = LN(h + p) * g2 + be2 ---------------------------
// One warp per row (256 cols = 2 float4 per lane). g_p already includes bl.
__global__ __launch_bounds__(256)
void k_ln2(const float* __restrict__ g2, const float* __restrict__ be2,
           float* __restrict__ out)
{
    int row  = blockIdx.x * 8 + (threadIdx.x >> 5);
    int lane = threadIdx.x & 31;
    if (row >= N_NODES) return;
    const float* hp = g_h + (size_t)row * D_OUT;
    const float* pp = g_p + (size_t)row * D_OUT;

    float4 v[2];
    float s = 0.f, q = 0.f;
#pragma unroll
    for (int j = 0; j < 2; j++) {
        int c = (lane + 32 * j) * 4;
        float4 a = *reinterpret_cast<const float4*>(hp + c);
        float4 b = *reinterpret_cast<const float4*>(pp + c);
        v[j] = make_float4(a.x + b.x, a.y + b.y, a.z + b.z, a.w + b.w);
        s += v[j].x + v[j].y + v[j].z + v[j].w;
        q += v[j].x * v[j].x + v[j].y * v[j].y + v[j].z * v[j].z + v[j].w * v[j].w;
    }
#pragma unroll
    for (int o = 16; o > 0; o >>= 1) {
        s += __shfl_xor_sync(0xffffffffu, s, o);
        q += __shfl_xor_sync(0xffffffffu, q, o);
    }
    float mu = s * (1.f / D_OUT);
    float rs = rsqrtf(q * (1.f / D_OUT) - mu * mu + 1e-5f);

#pragma unroll
    for (int j = 0; j < 2; j++) {
        int c = (lane + 32 * j) * 4;
        float4 gg = *reinterpret_cast<const float4*>(g2  + c);
        float4 bt = *reinterpret_cast<const float4*>(be2 + c);
        float4 o;
        o.x = (v[j].x - mu) * rs * gg.x + bt.x;
        o.y = (v[j].y - mu) * rs * gg.y + bt.y;
        o.z = (v[j].z - mu) * rs * gg.z + bt.z;
        o.w = (v[j].w - mu) * rs * gg.w + bt.w;
        *reinterpret_cast<float4*>(out + (size_t)row * D_OUT + c) = o;
    }
}

// ---------------- launch -----------------------------------------------------
extern "C" void kernel_launch(void* const* d_in, const int* in_sizes, int n_in,
                              void* d_out, int out_size)
{
    const float* x   = (const float*)d_in[0];
    const void*  ei  = d_in[1];
    const float* W1  = (const float*)d_in[2];
    const float* b1  = (const float*)d_in[3];
    const float* g1  = (const float*)d_in[4];
    const float* be1 = (const float*)d_in[5];
    const float* W2  = (const float*)d_in[6];
    const float* b2  = (const float*)d_in[7];
    const float* Wl  = (const float*)d_in[8];
    const float* bl  = (const float*)d_in[9];
    const float* Wr  = (const float*)d_in[10];
    const float* g2  = (const float*)d_in[11];
    const float* be2 = (const float*)d_in[12];
    float* out = (float*)d_out;

    (void)in_sizes; (void)n_in; (void)out_size;

    float *p_h1, *p_h, *p_sum, *p_inv, *p_p;
    cudaGetSymbolAddress((void**)&p_h1,  g_h1);
    cudaGetSymbolAddress((void**)&p_h,   g_h);
    cudaGetSymbolAddress((void**)&p_sum, g_sum);
    cudaGetSymbolAddress((void**)&p_inv, g_inv);
    cudaGetSymbolAddress((void**)&p_p,   g_p);

    const int MB = (N_NODES + 127) / 128;   // 782

    k_zero<<<2048, 256>>>(ei);

    // h1pre = x @ W1 + b1
    k_gemm<D_IN, D_HID, D_IN, false><<<dim3(D_HID / 64, MB), 128>>>(
        x, nullptr, W1, nullptr, nullptr, b1, p_h1);
    // h1 = GELU(LN(h1pre))
    k_ln1<<<N_NODES / 8, 256>>>(g1, be1);
    // h = h1 @ W2 + b2
    k_gemm<D_HID, D_OUT, D_HID, false><<<dim3(D_OUT / 64, MB), 128>>>(
        p_h1, nullptr, W2, nullptr, nullptr, b2, p_h);
    // segment sums + counts
    k_scatter<<<(N_EDGES * 32) / 256, 256>>>(ei);
    k_inv<<<(N_NODES + 255) / 256, 256>>>();
    // p = (sum * inv) @ Wl + h @ Wr + bl   (fused K=512 split GEMM)
    k_gemm<512, D_OUT, D_OUT, true><<<dim3(D_OUT / 64, MB), 128>>>(
        p_sum, p_h, Wl, Wr, p_inv, bl, p_p);
    // out = LN(h + p) * g2 + be2
    k_ln2<<<N_NODES / 8, 256>>>(g2, be2, out);
}

// round 15
// speedup vs baseline: 1.0021x; 1.0021x over previous
#include <cuda_runtime.h>
#include <math.h>
#include <stdint.h>

#define N_NODES 100000
#define N_EDGES 1600000
#define D_IN    384
#define D_HID   768
#define D_OUT   256

// ---------------- scratch (device globals: no allocation allowed) ----------
__device__ __align__(16) float g_h1 [(size_t)N_NODES * D_HID];  // 307 MB (pre-LN, then LN'd in place)
__device__ __align__(16) float g_h  [(size_t)N_NODES * D_OUT];  // 102 MB
__device__ __align__(16) float g_sum[(size_t)N_NODES * D_OUT];  // 102 MB
__device__ __align__(16) float g_p  [(size_t)N_NODES * D_OUT];  // 102 MB (sage pre-LN)
__device__ __align__(16) float g_cnt[N_NODES];
__device__ __align__(16) float g_inv[N_NODES];
__device__ int g_is64;

// ---------------- helpers ----------------------------------------------------
__device__ __forceinline__ float to_tf32(float x) {
    float r;
    asm("cvt.rna.tf32.f32 %0, %1;" : "=f"(r) : "f"(x));
    return r;
}

__device__ __forceinline__ void mma_tf32(float* c, const uint32_t* a, const uint32_t* b) {
    asm volatile(
        "mma.sync.aligned.m16n8k8.row.col.f32.tf32.tf32.f32 "
        "{%0,%1,%2,%3}, {%4,%5,%6,%7}, {%8,%9}, {%0,%1,%2,%3};\n"
        : "+f"(c[0]), "+f"(c[1]), "+f"(c[2]), "+f"(c[3])
        : "r"(a[0]), "r"(a[1]), "r"(a[2]), "r"(a[3]), "r"(b[0]), "r"(b[1]));
}

// ---------------- K0: zero accumulators + detect edge_index dtype ----------
__global__ void k_zero(const void* __restrict__ ei_raw)
{
    size_t i      = (size_t)blockIdx.x * blockDim.x + threadIdx.x;
    size_t stride = (size_t)gridDim.x * blockDim.x;
    size_t n4     = (size_t)N_NODES * D_OUT / 4;
    float4 z = make_float4(0.f, 0.f, 0.f, 0.f);
    for (size_t j = i; j < n4; j += stride)
        reinterpret_cast<float4*>(g_sum)[j] = z;
    for (size_t j = i; j < N_NODES; j += stride)
        g_cnt[j] = 0.f;

    if (blockIdx.x == 0 && threadIdx.x == 0) {
        const unsigned int* w = (const unsigned int*)ei_raw;
        int is64 = 1;
        for (int k = 0; k < 64; k++)
            if (w[2 * k + 1] != 0u) is64 = 0;
        g_is64 = is64;
    }
}

// ---------------- tf32 GEMM: C[M,NN] = A[M,KTOT] @ B[KTOT,NN] + bias ---------
// Block tile 128x64, 4 warps (2x2), each warp 64x32 (4x4 m16n8k8 tiles), BK=16.
// SPLIT: K in [0,256) reads A0*inv[row] with B0; K in [256,512) reads A1 with B1.
template<int KTOT, int NN, int AST, bool SPLIT>
__global__ __launch_bounds__(128)
void k_gemm(const float* __restrict__ A0, const float* __restrict__ A1,
            const float* __restrict__ B0, const float* __restrict__ B1,
            const float* __restrict__ inv, const float* __restrict__ bias,
            float* __restrict__ Cout)
{
    constexpr int BM = 128, BN = 64, BK = 16;
    constexpr int ASW = BM + 4;   // 132: conflict-free frag loads
    constexpr int BSW = BN + 4;   // 68

    __shared__ float As[BK][ASW];
    __shared__ float Bs[BK][BSW];

    const int bn0  = blockIdx.x * BN;
    const int bm0  = blockIdx.y * BM;
    const int tid  = threadIdx.x;
    const int lane = tid & 31, wid = tid >> 5;
    const int gid  = lane >> 2, tig = lane & 3;
    const int wm0  = (wid & 1) * 64;
    const int wn0  = (wid >> 1) * 32;

    // A loader: thread covers rows rb+32j (j=0..3), k-quad qi (4 consecutive k)
    const int qi = tid & 3;
    const int rb = tid >> 2;

    float4 ra[4];
    float4 rbv[2];
    float  acc[4][4][4];
#pragma unroll
    for (int mt = 0; mt < 4; mt++)
#pragma unroll
        for (int nt = 0; nt < 4; nt++)
#pragma unroll
            for (int j = 0; j < 4; j++) acc[mt][nt][j] = 0.f;

    auto loadA = [&](int k0) {
#pragma unroll
        for (int j = 0; j < 4; j++) {
            int row = bm0 + rb + 32 * j;
            float4 v = make_float4(0.f, 0.f, 0.f, 0.f);
            if (row < N_NODES) {
                if (!SPLIT || k0 < 256) {
                    v = *reinterpret_cast<const float4*>(A0 + (size_t)row * AST + k0 + qi * 4);
                    if (SPLIT) {
                        float s = inv[row];
                        v.x *= s; v.y *= s; v.z *= s; v.w *= s;
                    }
                } else {
                    v = *reinterpret_cast<const float4*>(A1 + (size_t)row * AST + (k0 - 256) + qi * 4);
                }
            }
            ra[j] = v;
        }
    };

    auto loadB = [&](int k0) {
#pragma unroll
        for (int j = 0; j < 2; j++) {
            int idx = tid + 128 * j;
            int kb = idx >> 4, nq = idx & 15;
            const float* Bp;
            if (!SPLIT || k0 < 256) Bp = B0 + (size_t)(k0 + kb) * NN;
            else                    Bp = B1 + (size_t)(k0 - 256 + kb) * NN;
            rbv[j] = *reinterpret_cast<const float4*>(Bp + bn0 + nq * 4);
        }
    };

    auto storeS = [&]() {
#pragma unroll
        for (int j = 0; j < 4; j++) {
            int r = rb + 32 * j;
            As[qi * 4 + 0][r] = to_tf32(ra[j].x);
            As[qi * 4 + 1][r] = to_tf32(ra[j].y);
            As[qi * 4 + 2][r] = to_tf32(ra[j].z);
            As[qi * 4 + 3][r] = to_tf32(ra[j].w);
        }
#pragma unroll
        for (int j = 0; j < 2; j++) {
            int idx = tid + 128 * j;
            int kb = idx >> 4, nq = idx & 15;
            float4 v = rbv[j];
            v.x = to_tf32(v.x); v.y = to_tf32(v.y);
            v.z = to_tf32(v.z); v.w = to_tf32(v.w);
            *reinterpret_cast<float4*>(&Bs[kb][nq * 4]) = v;
        }
    };

    auto compute = [&]() {
#pragma unroll
        for (int s = 0; s < 2; s++) {
            const int kk = s * 8;
            uint32_t af[4][4], bf[4][2];
#pragma unroll
            for (int mt = 0; mt < 4; mt++) {
                int m = wm0 + mt * 16 + gid;
                af[mt][0] = __float_as_uint(As[kk + tig    ][m]);
                af[mt][1] = __float_as_uint(As[kk + tig    ][m + 8]);
                af[mt][2] = __float_as_uint(As[kk + tig + 4][m]);
                af[mt][3] = __float_as_uint(As[kk + tig + 4][m + 8]);
            }
#pragma unroll
            for (int nt = 0; nt < 4; nt++) {
                int n = wn0 + nt * 8 + gid;
                bf[nt][0] = __float_as_uint(Bs[kk + tig    ][n]);
                bf[nt][1] = __float_as_uint(Bs[kk + tig + 4][n]);
            }
#pragma unroll
            for (int mt = 0; mt < 4; mt++)
#pragma unroll
                for (int nt = 0; nt < 4; nt++)
                    mma_tf32(acc[mt][nt], af[mt], bf[nt]);
        }
    };

    loadA(0);
    loadB(0);
    for (int k0 = 0; k0 < KTOT; k0 += BK) {
        __syncthreads();
        storeS();
        __syncthreads();
        if (k0 + BK < KTOT) { loadA(k0 + BK); loadB(k0 + BK); }
        compute();
    }

    // epilogue: + bias, store fp32
#pragma unroll
    for (int mt = 0; mt < 4; mt++) {
        int r0 = bm0 + wm0 + mt * 16 + gid;
#pragma unroll
        for (int nt = 0; nt < 4; nt++) {
            int c = bn0 + wn0 + nt * 8 + 2 * tig;
            float2 bv = *reinterpret_cast<const float2*>(bias + c);
            if (r0 < N_NODES) {
                float2 o = make_float2(acc[mt][nt][0] + bv.x, acc[mt][nt][1] + bv.y);
                *reinterpret_cast<float2*>(Cout + (size_t)r0 * NN + c) = o;
            }
            if (r0 + 8 < N_NODES) {
                float2 o = make_float2(acc[mt][nt][2] + bv.x, acc[mt][nt][3] + bv.y);
                *reinterpret_cast<float2*>(Cout + (size_t)(r0 + 8) * NN + c) = o;
            }
        }
    }
}

// ---------------- LN1: g_h1 = GELU(LN(g_h1) * g1 + be1), in place -----------
// One warp per row (768 cols = 6 float4 per lane).
__global__ __launch_bounds__(256)
void k_ln1(const float* __restrict__ g1, const float* __restrict__ be1)
{
    int row  = blockIdx.x * 8 + (threadIdx.x >> 5);
    int lane = threadIdx.x & 31;
    if (row >= N_NODES) return;
    float* p = g_h1 + (size_t)row * D_HID;

    float4 v[6];
    float s = 0.f, q = 0.f;
#pragma unroll
    for (int j = 0; j < 6; j++) {
        v[j] = *reinterpret_cast<const float4*>(p + (lane + 32 * j) * 4);
        s += v[j].x + v[j].y + v[j].z + v[j].w;
        q += v[j].x * v[j].x + v[j].y * v[j].y + v[j].z * v[j].z + v[j].w * v[j].w;
    }
#pragma unroll
    for (int o = 16; o > 0; o >>= 1) {
        s += __shfl_xor_sync(0xffffffffu, s, o);
        q += __shfl_xor_sync(0xffffffffu, q, o);
    }
    float mu = s * (1.f / D_HID);
    float rs = rsqrtf(q * (1.f / D_HID) - mu * mu + 1e-5f);

#pragma unroll
    for (int j = 0; j < 6; j++) {
        int c = (lane + 32 * j) * 4;
        float4 gg = *reinterpret_cast<const float4*>(g1  + c);
        float4 bt = *reinterpret_cast<const float4*>(be1 + c);
        float4 o;
        float t;
        t = (v[j].x - mu) * rs * gg.x + bt.x; o.x = 0.5f * t * (1.f + erff(t * 0.70710678118654752f));
        t = (v[j].y - mu) * rs * gg.y + bt.y; o.y = 0.5f * t * (1.f + erff(t * 0.70710678118654752f));
        t = (v[j].z - mu) * rs * gg.z + bt.z; o.z = 0.5f * t * (1.f + erff(t * 0.70710678118654752f));
        t = (v[j].w - mu) * rs * gg.w + bt.w; o.w = 0.5f * t * (1.f + erff(t * 0.70710678118654752f));
        *reinterpret_cast<float4*>(p + c) = o;
    }
}

// ---------------- K3: edge scatter (segment-sum + counts) -------------------
__global__ void k_scatter(const void* __restrict__ ei_raw)
{
    int gw   = (int)(((size_t)blockIdx.x * blockDim.x + threadIdx.x) >> 5);
    int lane = threadIdx.x & 31;
    if (gw >= N_EDGES) return;

    int s, d;
    if (g_is64) {
        const long long* e = (const long long*)ei_raw;
        s = (int)e[gw];
        d = (int)e[(size_t)N_EDGES + gw];
    } else {
        const int* e = (const int*)ei_raw;
        s = e[gw];
        d = e[N_EDGES + gw];
    }

    const float4* hp = reinterpret_cast<const float4*>(g_h + (size_t)s * D_OUT);
    float*        sp = g_sum + (size_t)d * D_OUT;

    float4 v0 = hp[lane];
    float4 v1 = hp[lane + 32];
    int b0 = lane * 4;
    atomicAdd(sp + b0 + 0, v0.x);
    atomicAdd(sp + b0 + 1, v0.y);
    atomicAdd(sp + b0 + 2, v0.z);
    atomicAdd(sp + b0 + 3, v0.w);
    atomicAdd(sp + 128 + b0 + 0, v1.x);
    atomicAdd(sp + 128 + b0 + 1, v1.y);
    atomicAdd(sp + 128 + b0 + 2, v1.z);
    atomicAdd(sp + 128 + b0 + 3, v1.w);
    if (lane == 0) atomicAdd(&g_cnt[d], 1.0f);
}

// ---------------- inv counts -------------------------------------------------
__global__ void k_inv()
{
    int i = blockIdx.x * 256 + threadIdx.x;
    if (i < N_NODES) g_inv[i] = 1.f / fmaxf(g_cnt[i], 1.f);
}

// ---------------- LN2: out = LN(h + p) * g2 + be2 ---------------------------
// One warp per row (256 cols = 2 float4 per lane). g_p already includes bl.
__global__ __launch_bounds__(256)
void k_ln2(const float* __restrict__ g2, const float* __restrict__ be2,
           float* __restrict__ out)
{
    int row  = blockIdx.x * 8 + (threadIdx.x >> 5);
    int lane = threadIdx.x & 31;
    if (row >= N_NODES) return;
    const float* hp = g_h + (size_t)row * D_OUT;
    const float* pp = g_p + (size_t)row * D_OUT;

    float4 v[2];
    float s = 0.f, q = 0.f;
#pragma unroll
    for (int j = 0; j < 2; j++) {
        int c = (lane + 32 * j) * 4;
        float4 a = *reinterpret_cast<const float4*>(hp + c);
        float4 b = *reinterpret_cast<const float4*>(pp + c);
        v[j] = make_float4(a.x + b.x, a.y + b.y, a.z + b.z, a.w + b.w);
        s += v[j].x + v[j].y + v[j].z + v[j].w;
        q += v[j].x * v[j].x + v[j].y * v[j].y + v[j].z * v[j].z + v[j].w * v[j].w;
    }
#pragma unroll
    for (int o = 16; o > 0; o >>= 1) {
        s += __shfl_xor_sync(0xffffffffu, s, o);
        q += __shfl_xor_sync(0xffffffffu, q, o);
    }
    float mu = s * (1.f / D_OUT);
    float rs = rsqrtf(q * (1.f / D_OUT) - mu * mu + 1e-5f);

#pragma unroll
    for (int j = 0; j < 2; j++) {
        int c = (lane + 32 * j) * 4;
        float4 gg = *reinterpret_cast<const float4*>(g2  + c);
        float4 bt = *reinterpret_cast<const float4*>(be2 + c);
        float4 o;
        o.x = (v[j].x - mu) * rs * gg.x + bt.x;
        o.y = (v[j].y - mu) * rs * gg.y + bt.y;
        o.z = (v[j].z - mu) * rs * gg.z + bt.z;
        o.w = (v[j].w - mu) * rs * gg.w + bt.w;
        *reinterpret_cast<float4*>(out + (size_t)row * D_OUT + c) = o;
    }
}

// ---------------- launch -----------------------------------------------------
extern "C" void kernel_launch(void* const* d_in, const int* in_sizes, int n_in,
                              void* d_out, int out_size)
{
    const float* x   = (const float*)d_in[0];
    const void*  ei  = d_in[1];
    const float* W1  = (const float*)d_in[2];
    const float* b1  = (const float*)d_in[3];
    const float* g1  = (const float*)d_in[4];
    const float* be1 = (const float*)d_in[5];
    const float* W2  = (const float*)d_in[6];
    const float* b2  = (const float*)d_in[7];
    const float* Wl  = (const float*)d_in[8];
    const float* bl  = (const float*)d_in[9];
    const float* Wr  = (const float*)d_in[10];
    const float* g2  = (const float*)d_in[11];
    const float* be2 = (const float*)d_in[12];
    float* out = (float*)d_out;

    (void)in_sizes; (void)n_in; (void)out_size;

    float *p_h1, *p_h, *p_sum, *p_inv, *p_p;
    cudaGetSymbolAddress((void**)&p_h1,  g_h1);
    cudaGetSymbolAddress((void**)&p_h,   g_h);
    cudaGetSymbolAddress((void**)&p_sum, g_sum);
    cudaGetSymbolAddress((void**)&p_inv, g_inv);
    cudaGetSymbolAddress((void**)&p_p,   g_p);

    const int MB = (N_NODES + 127) / 128;   // 782

    k_zero<<<2048, 256>>>(ei);

    // h1pre = x @ W1 + b1
    k_gemm<D_IN, D_HID, D_IN, false><<<dim3(D_HID / 64, MB), 128>>>(
        x, nullptr, W1, nullptr, nullptr, b1, p_h1);
    // h1 = GELU(LN(h1pre))
    k_ln1<<<N_NODES / 8, 256>>>(g1, be1);
    // h = h1 @ W2 + b2
    k_gemm<D_HID, D_OUT, D_HID, false><<<dim3(D_OUT / 64, MB), 128>>>(
        p_h1, nullptr, W2, nullptr, nullptr, b2, p_h);
    // segment sums + counts
    k_scatter<<<(N_EDGES * 32) / 256, 256>>>(ei);
    k_inv<<<(N_NODES + 255) / 256, 256>>>();
    // p = (sum * inv) @ Wl + h @ Wr + bl   (fused K=512 split GEMM)
    k_gemm<512, D_OUT, D_OUT, true><<<dim3(D_OUT / 64, MB), 128>>>(
        p_sum, p_h, Wl, Wr, p_inv, bl, p_p);
    // out = LN(h + p) * g2 + be2
    k_ln2<<<N_NODES / 8, 256>>>(g2, be2, out);
}